// round 16
// baseline (speedup 1.0000x reference)
#include <cuda_runtime.h>
#include <cstdint>

#define Bc 16
#define Nc 256
#define Dc 128
#define Lc 3
#define Ec 32768
#define BN (Bc*Nc)            // 4096
#define ADJ_ELEMS (Bc*Nc*Nc)  // 1,048,576

typedef unsigned long long u64;

// ---------------- scratch ---------------------------------------------------
__device__ float  g_adj[ADJ_ELEMS];   // 4 MB
__device__ float  g_h  [BN*Dc];
__device__ float  g_ht [BN*Dc];
__device__ float  g_hs [BN*Dc];
__device__ float  g_p  [BN*Dc];
__device__ float  g_q  [BN*Dc];
__device__ float4 g_amr[BN*Nc];       // 16 MB  {a, r, -mu*r, 0} per pair
__device__ float4 g_statT[BN];        // {S/128, Q, 2*T, 0}
__device__ float4 g_statS[BN];
__device__ float  g_wstat[2*Lc];      // per layer {Swj/128, Qwj}

// ---------------- helpers ---------------------------------------------------
__device__ __forceinline__ float silu_f(float y) {
    return __fdividef(y, 1.0f + __expf(-y));
}
__device__ __forceinline__ float tanh_ap(float x) {
    float r; asm("tanh.approx.f32 %0,%1;" : "=f"(r) : "f"(x)); return r;
}
__device__ __forceinline__ u64 pk2(float lo, float hi) {
    u64 r; asm("mov.b64 %0,{%1,%2};" : "=l"(r) : "f"(lo), "f"(hi)); return r;
}
__device__ __forceinline__ void upk2(u64 v, float& lo, float& hi) {
    asm("mov.b64 {%0,%1},%2;" : "=f"(lo), "=f"(hi) : "l"(v));
}
__device__ __forceinline__ u64 fma2v(u64 a, u64 b, u64 c) {
    u64 d; asm("fma.rn.f32x2 %0,%1,%2,%3;" : "=l"(d) : "l"(a), "l"(b), "l"(c)); return d;
}
__device__ __forceinline__ u64 add2v(u64 a, u64 b) {
    u64 d; asm("add.rn.f32x2 %0,%1,%2;" : "=l"(d) : "l"(a), "l"(b)); return d;
}

// ---------------- prep: zero adj + encode + wstat (one launch) ---------------
__global__ void __launch_bounds__(256) prep_kernel(
        const float* __restrict__ x,
        const float* __restrict__ encW,
        const float* __restrict__ encb,
        const float* __restrict__ msgW,
        float* __restrict__ adj,
        float* __restrict__ h,
        float* __restrict__ wst) {
    int b = blockIdx.x;
    int t = threadIdx.x;
    if (b < 1024) {
        *(float4*)(adj + b * 1024 + t * 4) = make_float4(0.f, 0.f, 0.f, 0.f);
    } else if (b < 1088) {
        int base = (b - 1024) * 8192;
#pragma unroll
        for (int c = 0; c < 32; c++) {
            int gi = base + c * 256 + t;
            int i = gi >> 7, d = gi & 127;
            h[gi] = fmaf(x[i], encW[d], encb[d]);
        }
    } else {
        int l = t >> 5, lane = t & 31;
        if (l >= Lc) return;
        const float* wj = msgW + (size_t)l * 257 * Dc + 2 * Dc * Dc;
        float s = 0.f, q = 0.f;
#pragma unroll
        for (int c = 0; c < 4; c++) {
            float v = wj[c * 32 + lane];
            s += v; q = fmaf(v, v, q);
        }
#pragma unroll
        for (int o = 16; o; o >>= 1) {
            s += __shfl_xor_sync(0xffffffffu, s, o);
            q += __shfl_xor_sync(0xffffffffu, q, o);
        }
        if (lane == 0) { wst[l * 2] = s * (1.0f / 128.0f); wst[l * 2 + 1] = q; }
    }
}

__global__ void scatter_adj_kernel(const int* __restrict__ ei,
                                   const float* __restrict__ ea,
                                   float* __restrict__ adj) {
    int e = blockIdx.x * blockDim.x + threadIdx.x;
    if (e >= Ec) return;
    int u = ei[e];
    int v = ei[Ec + e];
    int b = u >> 8;
    int s = u & 255;
    int d = v & 255;
    float w = ea[e];
    atomicAdd(&adj[(b << 16) + (s << 8) + d], w);
    atomicAdd(&adj[(b << 16) + (d << 8) + s], w);
}

// ---------------- dual GEMM, wg-split, optional fused node-stats ------------
template <bool STATS>
__global__ void __launch_bounds__(256) dual_mm_ns(
        const float* __restrict__ X,
        const float* __restrict__ W1,
        const float* __restrict__ W2,
        const float* __restrict__ b1,
        const float* __restrict__ wj,
        float* __restrict__ O1, float* __restrict__ O2,
        float4* __restrict__ statT, float4* __restrict__ statS) {
    __shared__ float xs[8][132];
    __shared__ float red[2][4][8][3];
    int base = blockIdx.x * 8;
    int t = threadIdx.x;
    int wg = t >> 7, tl = t & 127;
#pragma unroll
    for (int c = 0; c < 4; c++) {
        int idx = c * 256 + t;             // 0..1023
        xs[idx >> 7][idx & 127] = X[base * Dc + idx];
    }
    __syncthreads();
    const float* W = wg ? W2 : W1;
    float acc[8];
    float bv = wg ? 0.0f : b1[tl];
#pragma unroll
    for (int r = 0; r < 8; r++) acc[r] = bv;
#pragma unroll 4
    for (int k4 = 0; k4 < 32; k4++) {
        float wk[4];
#pragma unroll
        for (int kk = 0; kk < 4; kk++) wk[kk] = W[(k4 * 4 + kk) * Dc + tl];
#pragma unroll
        for (int r = 0; r < 8; r++) {
            float4 x4 = *(float4*)&xs[r][k4 * 4];
            acc[r] = fmaf(x4.x, wk[0], acc[r]);
            acc[r] = fmaf(x4.y, wk[1], acc[r]);
            acc[r] = fmaf(x4.z, wk[2], acc[r]);
            acc[r] = fmaf(x4.w, wk[3], acc[r]);
        }
    }
    float* O = wg ? O2 : O1;
#pragma unroll
    for (int r = 0; r < 8; r++) O[(base + r) * Dc + tl] = acc[r];

    if constexpr (STATS) {
        float wv = wj[tl];
        int lane = t & 31, warp = (t >> 5) & 3;
#pragma unroll
        for (int r = 0; r < 8; r++) {
            float s = acc[r], q = acc[r] * acc[r], tt = acc[r] * wv;
#pragma unroll
            for (int o = 16; o; o >>= 1) {
                s  += __shfl_xor_sync(0xffffffffu, s,  o);
                q  += __shfl_xor_sync(0xffffffffu, q,  o);
                tt += __shfl_xor_sync(0xffffffffu, tt, o);
            }
            if (lane == 0) {
                red[wg][warp][r][0] = s;
                red[wg][warp][r][1] = q;
                red[wg][warp][r][2] = tt;
            }
        }
        __syncthreads();
        if (t < 16) {
            int gi = t >> 3, r = t & 7;
            float s = 0.f, q = 0.f, tt = 0.f;
#pragma unroll
            for (int w = 0; w < 4; w++) {
                s  += red[gi][w][r][0];
                q  += red[gi][w][r][1];
                tt += red[gi][w][r][2];
            }
            float4 v = make_float4(s * (1.0f / 128.0f), q, 2.0f * tt, 0.0f);
            if (gi == 0) statT[base + r] = v; else statS[base + r] = v;
        }
    }
}

// ---------------- fused C=ht.hs + LN pair-stats -> amr ----------------------
// R9 tiling (best measured): 32i x 64j, 256 threads; thread = (4 i, j=l & l+32).
__global__ void __launch_bounds__(256) cdot_mr_kernel(
        const float* __restrict__ ht,
        const float* __restrict__ hs,
        const float* __restrict__ adj,
        const float4* __restrict__ statT,
        const float4* __restrict__ statS,
        const float* __restrict__ wstat,
        float4* __restrict__ amr) {
    extern __shared__ float dsm[];
    float* hts = dsm;                 // 32*132
    float* hss = dsm + 32 * 132;      // 64*132
    int base  = blockIdx.x * 32;      // i base
    int b     = base >> 8;
    int jbase = blockIdx.y * 64;
    int t = threadIdx.x;
#pragma unroll
    for (int c = 0; c < 4; c++) {     // hts: 4096 floats
        int idx = c * 1024 + t * 4;
        int row = idx >> 7, col = idx & 127;
        *(float4*)&hts[row * 132 + col] = *(const float4*)(ht + base * Dc + idx);
    }
#pragma unroll
    for (int c = 0; c < 8; c++) {     // hss: 8192 floats
        int idx = c * 1024 + t * 4;
        int row = idx >> 7, col = idx & 127;
        *(float4*)&hss[row * 132 + col] =
            *(const float4*)(hs + (b * Nc + jbase) * Dc + idx);
    }
    __syncthreads();

    int w = t >> 5, l = t & 31;
    int rbase = w * 4;                // this warp's 4 i-rows
    float acc[8];                     // [i][jj]: i*2+jj, jj=0 -> j=l, jj=1 -> j=l+32
#pragma unroll
    for (int r = 0; r < 8; r++) acc[r] = 0.0f;
#pragma unroll 2
    for (int k4 = 0; k4 < 32; k4++) {
        float4 h0 = *(float4*)&hss[l * 132 + k4 * 4];
        float4 h1 = *(float4*)&hss[(l + 32) * 132 + k4 * 4];
#pragma unroll
        for (int i = 0; i < 4; i++) {
            float4 x4 = *(float4*)&hts[(rbase + i) * 132 + k4 * 4];
            float a0 = acc[i * 2], a1 = acc[i * 2 + 1];
            a0 = fmaf(x4.x, h0.x, a0); a1 = fmaf(x4.x, h1.x, a1);
            a0 = fmaf(x4.y, h0.y, a0); a1 = fmaf(x4.y, h1.y, a1);
            a0 = fmaf(x4.z, h0.z, a0); a1 = fmaf(x4.z, h1.z, a1);
            a0 = fmaf(x4.w, h0.w, a0); a1 = fmaf(x4.w, h1.w, a1);
            acc[i * 2] = a0; acc[i * 2 + 1] = a1;
        }
    }

    float Sw = __ldg(wstat), Qw = __ldg(wstat + 1);
#pragma unroll
    for (int jj = 0; jj < 2; jj++) {
        int j = jbase + l + jj * 32;
        float4 S = statS[b * Nc + j];
#pragma unroll
        for (int i = 0; i < 4; i++) {
            int row = base + rbase + i;
            float4 T = __ldg(statT + row);           // broadcast within warp
            float a  = adj[row * Nc + j];
            float mu   = fmaf(a, Sw, T.x + S.x);
            float sq   = fmaf(2.0f, acc[i * 2 + jj], T.y + S.y);
            sq         = fmaf(a, fmaf(a, Qw, T.z + S.z), sq);
            float var  = fmaf(sq, 1.0f / 128.0f, -mu * mu);
            float rv   = rsqrtf(var + 1e-5f);
            amr[row * Nc + j] = make_float4(a, rv, -mu * rv, 0.0f);
        }
    }
}

// ---------------- fused message + update ------------------------------------
__global__ void __launch_bounds__(256) msg_upd_kernel(
        const float* __restrict__ ht,
        const float* __restrict__ hs,
        const float* __restrict__ wjv,
        const float* __restrict__ g,
        const float* __restrict__ be,
        const float4* __restrict__ amr,
        float* __restrict__ h,
        const float* __restrict__ Wu,
        const float* __restrict__ bu,
        const float* __restrict__ ug,
        const float* __restrict__ ube) {
    __shared__ float cat[8][260];
    __shared__ float part[8][132];
    __shared__ float ubuf[8][132];
    int t = threadIdx.x;
    int warp = t >> 5;
    int lane = t & 31;
    int base = blockIdx.x * 8;
    int node = base + warp;
    int b = base >> 8;
    int i = node & 255;
    int d4 = lane << 2;

#pragma unroll
    for (int c = 0; c < 4; c++) {
        int idx = c * 256 + t;
        cat[idx >> 7][idx & 127] = h[base * Dc + idx];
    }

    // ---- msg phase ----
    const ulonglong2 HT = *(const ulonglong2*)(ht + node * Dc + d4);
    const ulonglong2 WJ = *(const ulonglong2*)(wjv + d4);
    float4 G4 = *(const float4*)(g + d4);
    float4 B4 = *(const float4*)(be + d4);
    u64 Gh01 = pk2(0.5f * G4.x, 0.5f * G4.y);
    u64 Gh23 = pk2(0.5f * G4.z, 0.5f * G4.w);
    u64 Bh01 = pk2(0.5f * B4.x, 0.5f * B4.y);
    u64 Bh23 = pk2(0.5f * B4.z, 0.5f * B4.w);

    const float* hsb = hs + b * Nc * Dc;
    const float4* arow = amr + node * Nc;

    u64 aP0 = 0, aP1 = 0, aT0 = 0, aT1 = 0;

#pragma unroll 8
    for (int j = 0; j < Nc; j++) {
        float4 m = __ldg(arow + j);              // {a, r, -mu*r, _}
        ulonglong2 sv = *(const ulonglong2*)(hsb + j * Dc + d4);
        u64 a2  = pk2(m.x, m.x);
        u64 r2  = pk2(m.y, m.y);
        u64 nm2 = pk2(m.z, m.z);
        u64 p0  = fma2v(a2, WJ.x, add2v(HT.x, sv.x));
        u64 p1  = fma2v(a2, WJ.y, add2v(HT.y, sv.y));
        u64 z0  = fma2v(p0, r2, nm2);
        u64 z1  = fma2v(p1, r2, nm2);
        u64 y0  = fma2v(z0, Gh01, Bh01);
        u64 y1  = fma2v(z1, Gh23, Bh23);
        float f0, f1, f2, f3;
        upk2(y0, f0, f1); upk2(y1, f2, f3);
        u64 t0 = pk2(tanh_ap(f0), tanh_ap(f1));
        u64 t1 = pk2(tanh_ap(f2), tanh_ap(f3));
        aP0 = add2v(aP0, y0);  aP1 = add2v(aP1, y1);
        aT0 = fma2v(y0, t0, aT0);
        aT1 = fma2v(y1, t1, aT1);
    }

    float ax, ay, az, aw;
    upk2(add2v(aP0, aT0), ax, ay);
    upk2(add2v(aP1, aT1), az, aw);

    // subtract diagonal j == i
    {
        float4 m = arow[i];
        const float4 s = *(const float4*)(hsb + i * Dc + d4);
        float h0, h1, h2, h3, w0, w1, w2, w3, g0, g1, g2, g3, e0, e1, e2, e3;
        upk2(HT.x, h0, h1); upk2(HT.y, h2, h3);
        upk2(WJ.x, w0, w1); upk2(WJ.y, w2, w3);
        upk2(Gh01, g0, g1); upk2(Gh23, g2, g3);
        upk2(Bh01, e0, e1); upk2(Bh23, e2, e3);
        float a = m.x, r = m.y, nmr = m.z;
        float p, z, y2;
        p = fmaf(a, w0, h0 + s.x); z = fmaf(p, r, nmr); y2 = fmaf(z, g0, e0); ax -= fmaf(y2, tanh_ap(y2), y2);
        p = fmaf(a, w1, h1 + s.y); z = fmaf(p, r, nmr); y2 = fmaf(z, g1, e1); ay -= fmaf(y2, tanh_ap(y2), y2);
        p = fmaf(a, w2, h2 + s.z); z = fmaf(p, r, nmr); y2 = fmaf(z, g2, e2); az -= fmaf(y2, tanh_ap(y2), y2);
        p = fmaf(a, w3, h3 + s.w); z = fmaf(p, r, nmr); y2 = fmaf(z, g3, e3); aw -= fmaf(y2, tanh_ap(y2), y2);
    }
    *(float4*)&cat[warp][Dc + d4] = make_float4(ax, ay, az, aw);
    __syncthreads();

    // ---- update phase: split-K GEMM ----
    int wg = t >> 7, tl = t & 127;
    float acc[8];
    float bv = wg ? 0.0f : bu[tl];
#pragma unroll
    for (int r = 0; r < 8; r++) acc[r] = bv;
    const float* Wp = Wu + wg * Dc * Dc;
    int kb = wg * Dc;
#pragma unroll 4
    for (int k4 = 0; k4 < 32; k4++) {
        float wk[4];
#pragma unroll
        for (int kk = 0; kk < 4; kk++) wk[kk] = Wp[(k4 * 4 + kk) * Dc + tl];
#pragma unroll
        for (int r = 0; r < 8; r++) {
            float4 x4 = *(float4*)&cat[r][kb + k4 * 4];
            acc[r] = fmaf(x4.x, wk[0], acc[r]);
            acc[r] = fmaf(x4.y, wk[1], acc[r]);
            acc[r] = fmaf(x4.z, wk[2], acc[r]);
            acc[r] = fmaf(x4.w, wk[3], acc[r]);
        }
    }
    if (wg == 1) {
#pragma unroll
        for (int r = 0; r < 8; r++) part[r][tl] = acc[r];
    }
    __syncthreads();
    if (wg == 0) {
#pragma unroll
        for (int r = 0; r < 8; r++) ubuf[r][tl] = acc[r] + part[r][tl];
    }
    __syncthreads();
    float4 u4 = *(float4*)&ubuf[warp][lane * 4];
    float s = (u4.x + u4.y) + (u4.z + u4.w);
    float q = fmaf(u4.x, u4.x, fmaf(u4.y, u4.y, fmaf(u4.z, u4.z, u4.w * u4.w)));
#pragma unroll
    for (int o = 16; o; o >>= 1) {
        s += __shfl_xor_sync(0xffffffffu, s, o);
        q += __shfl_xor_sync(0xffffffffu, q, o);
    }
    float mu  = s * (1.0f / 128.0f);
    float var = fmaf(q, 1.0f / 128.0f, -mu * mu);
    float rv  = rsqrtf(var + 1e-5f);
    float4 g4  = *(const float4*)(ug + lane * 4);
    float4 be4 = *(const float4*)(ube + lane * 4);
    float4 c4  = *(float4*)&cat[warp][lane * 4];
    float4 o4;
    o4.x = c4.x + silu_f(fmaf((u4.x - mu) * rv, g4.x, be4.x));
    o4.y = c4.y + silu_f(fmaf((u4.y - mu) * rv, g4.y, be4.y));
    o4.z = c4.z + silu_f(fmaf((u4.z - mu) * rv, g4.z, be4.z));
    o4.w = c4.w + silu_f(fmaf((u4.w - mu) * rv, g4.w, be4.w));
    *(float4*)(h + node * Dc + lane * 4) = o4;
}

// ---------------- fused decoder: e1 on the fly + 2-layer MLP ----------------
__global__ void __launch_bounds__(256) edge_kernel(
        const float* __restrict__ p, const float* __restrict__ q,
        const int* __restrict__ ei, const float* __restrict__ ea,
        const float* __restrict__ w1c,
        const float* __restrict__ W2,
        const float* __restrict__ b2,
        const float* __restrict__ w3,
        const float* __restrict__ b3,
        float* __restrict__ out) {
    __shared__ float2 W2s[Dc * 32];
    __shared__ float w1cs[Dc];
    __shared__ float w3s[64], b2s[64];
    __shared__ float e1s[8][132];
    int t = threadIdx.x;
    for (int i = t; i < Dc * 32; i += 256) {
        int k = i >> 5, c = i & 31;
        W2s[i] = make_float2(W2[k * 64 + c], W2[k * 64 + c + 32]);
    }
    if (t < Dc) w1cs[t] = w1c[t];
    if (t < 64) { w3s[t] = w3[t]; b2s[t] = b2[t]; }
    __syncthreads();
    float b3v = b3[0];
    int warp = t >> 5, lane = t & 31;
    int gw = blockIdx.x * 8 + warp;
    int nW = gridDim.x * 8;
    for (int e = gw; e < Ec; e += nW) {
        int u = ei[e];
        int v = ei[Ec + e];
        float a = ea[e];
        float4 pv = *(const float4*)(p + u * Dc + lane * 4);
        float4 qv = *(const float4*)(q + v * Dc + lane * 4);
        float4 wc = *(const float4*)(w1cs + lane * 4);
        float4 y;
        y.x = silu_f(fmaf(a, wc.x, pv.x + qv.x));
        y.y = silu_f(fmaf(a, wc.y, pv.y + qv.y));
        y.z = silu_f(fmaf(a, wc.z, pv.z + qv.z));
        y.w = silu_f(fmaf(a, wc.w, pv.w + qv.w));
        *(float4*)&e1s[warp][lane * 4] = y;
        __syncwarp();
        float a0 = b2s[lane], a1 = b2s[lane + 32];
#pragma unroll 4
        for (int k4 = 0; k4 < 32; k4++) {
            float4 s4 = *(float4*)&e1s[warp][k4 * 4];
            float2 w0 = W2s[(k4 * 4 + 0) * 32 + lane];
            float2 w1 = W2s[(k4 * 4 + 1) * 32 + lane];
            float2 w2 = W2s[(k4 * 4 + 2) * 32 + lane];
            float2 w3v = W2s[(k4 * 4 + 3) * 32 + lane];
            a0 = fmaf(s4.x, w0.x, a0); a1 = fmaf(s4.x, w0.y, a1);
            a0 = fmaf(s4.y, w1.x, a0); a1 = fmaf(s4.y, w1.y, a1);
            a0 = fmaf(s4.z, w2.x, a0); a1 = fmaf(s4.z, w2.y, a1);
            a0 = fmaf(s4.w, w3v.x, a0); a1 = fmaf(s4.w, w3v.y, a1);
        }
        a0 = silu_f(a0);
        a1 = silu_f(a1);
        float tt = fmaf(a0, w3s[lane], a1 * w3s[lane + 32]);
#pragma unroll
        for (int o = 16; o; o >>= 1) tt += __shfl_xor_sync(0xffffffffu, tt, o);
        if (lane == 0) out[e] = tanhf(tt + b3v);
        __syncwarp();
    }
}

// ---------------- launch ----------------------------------------------------
extern "C" void kernel_launch(void* const* d_in, const int* in_sizes, int n_in,
                              void* d_out, int out_size) {
    const float* x     = (const float*)d_in[0];
    const int*   ei    = (const int*)  d_in[1];
    const float* ea    = (const float*)d_in[2];
    const float* encW  = (const float*)d_in[4];
    const float* encb  = (const float*)d_in[5];
    const float* msgW  = (const float*)d_in[6];
    const float* msgb  = (const float*)d_in[7];
    const float* msgg  = (const float*)d_in[8];
    const float* msgbe = (const float*)d_in[9];
    const float* updW  = (const float*)d_in[10];
    const float* updb  = (const float*)d_in[11];
    const float* updg  = (const float*)d_in[12];
    const float* updbe = (const float*)d_in[13];
    const float* decW1 = (const float*)d_in[14];
    const float* decb1 = (const float*)d_in[15];
    const float* decW2 = (const float*)d_in[16];
    const float* decb2 = (const float*)d_in[17];
    const float* decW3 = (const float*)d_in[18];
    const float* decb3 = (const float*)d_in[19];
    float* out = (float*)d_out;

    float *adj, *h, *ht, *hs, *p, *q, *wst;
    float4 *amr, *sT, *sS;
    cudaGetSymbolAddress((void**)&adj, g_adj);
    cudaGetSymbolAddress((void**)&h,   g_h);
    cudaGetSymbolAddress((void**)&ht,  g_ht);
    cudaGetSymbolAddress((void**)&hs,  g_hs);
    cudaGetSymbolAddress((void**)&p,   g_p);
    cudaGetSymbolAddress((void**)&q,   g_q);
    cudaGetSymbolAddress((void**)&amr, g_amr);
    cudaGetSymbolAddress((void**)&sT,  g_statT);
    cudaGetSymbolAddress((void**)&sS,  g_statS);
    cudaGetSymbolAddress((void**)&wst, g_wstat);

    const int CDOT_SMEM = (32 * 132 + 64 * 132) * 4;   // 50688 B
    cudaFuncSetAttribute(cdot_mr_kernel,
                         cudaFuncAttributeMaxDynamicSharedMemorySize,
                         CDOT_SMEM);

    prep_kernel<<<1089, 256>>>(x, encW, encb, msgW, adj, h, wst);
    scatter_adj_kernel<<<(Ec + 255) / 256, 256>>>(ei, ea, adj);

    for (int l = 0; l < Lc; l++) {
        const float* Wl  = msgW + (size_t)l * 257 * Dc;
        const float* wjv = Wl + 2 * Dc * Dc;
        dual_mm_ns<true><<<BN / 8, 256>>>(h, Wl, Wl + Dc * Dc, msgb + l * Dc,
                                          wjv, ht, hs, sT, sS);
        cdot_mr_kernel<<<dim3(BN / 32, Nc / 64), 256, CDOT_SMEM>>>(
            ht, hs, adj, sT, sS, wst + 2 * l, amr);
        msg_upd_kernel<<<BN / 8, 256>>>(ht, hs, wjv,
                                        msgg + l * Dc, msgbe + l * Dc, amr, h,
                                        updW + (size_t)l * 2 * Dc * Dc,
                                        updb + l * Dc, updg + l * Dc, updbe + l * Dc);
    }

    dual_mm_ns<false><<<BN / 8, 256>>>(h, decW1, decW1 + Dc * Dc, decb1,
                                       nullptr, p, q, nullptr, nullptr);
    edge_kernel<<<512, 256>>>(p, q, ei, ea, decW1 + 2 * Dc * Dc,
                              decW2, decb2, decW3, decb3, out);
}

// round 17
// speedup vs baseline: 1.1376x; 1.1376x over previous
#include <cuda_runtime.h>
#include <cstdint>

#define Bc 16
#define Nc 256
#define Dc 128
#define Lc 3
#define Ec 32768
#define BN (Bc*Nc)            // 4096
#define ADJ_ELEMS (Bc*Nc*Nc)  // 1,048,576

typedef unsigned long long u64;

// ---------------- scratch ---------------------------------------------------
__device__ float  g_adj[ADJ_ELEMS];   // 4 MB
__device__ float  g_h  [BN*Dc];
__device__ float  g_ht [BN*Dc];
__device__ float  g_hs [BN*Dc];
__device__ float  g_p  [BN*Dc];
__device__ float  g_q  [BN*Dc];
__device__ float4 g_amr[BN*Nc];       // 16 MB  {a, r, -mu*r, 0} per pair
__device__ float4 g_statT[BN];        // {S/128, Q, 2*T, 0}
__device__ float4 g_statS[BN];
__device__ float  g_wstat[2*Lc];      // per layer {Swj/128, Qwj}

// ---------------- helpers ---------------------------------------------------
__device__ __forceinline__ float silu_f(float y) {
    return __fdividef(y, 1.0f + __expf(-y));
}
__device__ __forceinline__ float tanh_ap(float x) {
    float r; asm("tanh.approx.f32 %0,%1;" : "=f"(r) : "f"(x)); return r;
}
__device__ __forceinline__ u64 pk2(float lo, float hi) {
    u64 r; asm("mov.b64 %0,{%1,%2};" : "=l"(r) : "f"(lo), "f"(hi)); return r;
}
__device__ __forceinline__ void upk2(u64 v, float& lo, float& hi) {
    asm("mov.b64 {%0,%1},%2;" : "=f"(lo), "=f"(hi) : "l"(v));
}
__device__ __forceinline__ u64 fma2v(u64 a, u64 b, u64 c) {
    u64 d; asm("fma.rn.f32x2 %0,%1,%2,%3;" : "=l"(d) : "l"(a), "l"(b), "l"(c)); return d;
}
__device__ __forceinline__ u64 add2v(u64 a, u64 b) {
    u64 d; asm("add.rn.f32x2 %0,%1,%2;" : "=l"(d) : "l"(a), "l"(b)); return d;
}

// ---------------- prep: zero adj + encode + wstat (one launch) ---------------
__global__ void __launch_bounds__(256) prep_kernel(
        const float* __restrict__ x,
        const float* __restrict__ encW,
        const float* __restrict__ encb,
        const float* __restrict__ msgW,
        float* __restrict__ adj,
        float* __restrict__ h,
        float* __restrict__ wst) {
    int b = blockIdx.x;
    int t = threadIdx.x;
    if (b < 1024) {
        *(float4*)(adj + b * 1024 + t * 4) = make_float4(0.f, 0.f, 0.f, 0.f);
    } else if (b < 1088) {
        int base = (b - 1024) * 8192;
#pragma unroll
        for (int c = 0; c < 32; c++) {
            int gi = base + c * 256 + t;
            int i = gi >> 7, d = gi & 127;
            h[gi] = fmaf(x[i], encW[d], encb[d]);
        }
    } else {
        int l = t >> 5, lane = t & 31;
        if (l >= Lc) return;
        const float* wj = msgW + (size_t)l * 257 * Dc + 2 * Dc * Dc;
        float s = 0.f, q = 0.f;
#pragma unroll
        for (int c = 0; c < 4; c++) {
            float v = wj[c * 32 + lane];
            s += v; q = fmaf(v, v, q);
        }
#pragma unroll
        for (int o = 16; o; o >>= 1) {
            s += __shfl_xor_sync(0xffffffffu, s, o);
            q += __shfl_xor_sync(0xffffffffu, q, o);
        }
        if (lane == 0) { wst[l * 2] = s * (1.0f / 128.0f); wst[l * 2 + 1] = q; }
    }
}

__global__ void scatter_adj_kernel(const int* __restrict__ ei,
                                   const float* __restrict__ ea,
                                   float* __restrict__ adj) {
    int e = blockIdx.x * blockDim.x + threadIdx.x;
    if (e >= Ec) return;
    int u = ei[e];
    int v = ei[Ec + e];
    int b = u >> 8;
    int s = u & 255;
    int d = v & 255;
    float w = ea[e];
    atomicAdd(&adj[(b << 16) + (s << 8) + d], w);
    atomicAdd(&adj[(b << 16) + (d << 8) + s], w);
}

// ---------------- dual GEMM, wg-split, optional fused node-stats ------------
template <bool STATS>
__global__ void __launch_bounds__(256) dual_mm_ns(
        const float* __restrict__ X,
        const float* __restrict__ W1,
        const float* __restrict__ W2,
        const float* __restrict__ b1,
        const float* __restrict__ wj,
        float* __restrict__ O1, float* __restrict__ O2,
        float4* __restrict__ statT, float4* __restrict__ statS) {
    __shared__ float xs[8][132];
    __shared__ float red[2][4][8][3];
    int base = blockIdx.x * 8;
    int t = threadIdx.x;
    int wg = t >> 7, tl = t & 127;
#pragma unroll
    for (int c = 0; c < 4; c++) {
        int idx = c * 256 + t;             // 0..1023
        xs[idx >> 7][idx & 127] = X[base * Dc + idx];
    }
    __syncthreads();
    const float* W = wg ? W2 : W1;
    float acc[8];
    float bv = wg ? 0.0f : b1[tl];
#pragma unroll
    for (int r = 0; r < 8; r++) acc[r] = bv;
#pragma unroll 4
    for (int k4 = 0; k4 < 32; k4++) {
        float wk[4];
#pragma unroll
        for (int kk = 0; kk < 4; kk++) wk[kk] = W[(k4 * 4 + kk) * Dc + tl];
#pragma unroll
        for (int r = 0; r < 8; r++) {
            float4 x4 = *(float4*)&xs[r][k4 * 4];
            acc[r] = fmaf(x4.x, wk[0], acc[r]);
            acc[r] = fmaf(x4.y, wk[1], acc[r]);
            acc[r] = fmaf(x4.z, wk[2], acc[r]);
            acc[r] = fmaf(x4.w, wk[3], acc[r]);
        }
    }
    float* O = wg ? O2 : O1;
#pragma unroll
    for (int r = 0; r < 8; r++) O[(base + r) * Dc + tl] = acc[r];

    if constexpr (STATS) {
        float wv = wj[tl];
        int lane = t & 31, warp = (t >> 5) & 3;
#pragma unroll
        for (int r = 0; r < 8; r++) {
            float s = acc[r], q = acc[r] * acc[r], tt = acc[r] * wv;
#pragma unroll
            for (int o = 16; o; o >>= 1) {
                s  += __shfl_xor_sync(0xffffffffu, s,  o);
                q  += __shfl_xor_sync(0xffffffffu, q,  o);
                tt += __shfl_xor_sync(0xffffffffu, tt, o);
            }
            if (lane == 0) {
                red[wg][warp][r][0] = s;
                red[wg][warp][r][1] = q;
                red[wg][warp][r][2] = tt;
            }
        }
        __syncthreads();
        if (t < 16) {
            int gi = t >> 3, r = t & 7;
            float s = 0.f, q = 0.f, tt = 0.f;
#pragma unroll
            for (int w = 0; w < 4; w++) {
                s  += red[gi][w][r][0];
                q  += red[gi][w][r][1];
                tt += red[gi][w][r][2];
            }
            float4 v = make_float4(s * (1.0f / 128.0f), q, 2.0f * tt, 0.0f);
            if (gi == 0) statT[base + r] = v; else statS[base + r] = v;
        }
    }
}

// ---------------- fused C=ht.hs + LN pair-stats -> amr ----------------------
// R9 tiling (best measured): 32i x 64j, 256 threads; thread = (4 i, j=l & l+32).
__global__ void __launch_bounds__(256) cdot_mr_kernel(
        const float* __restrict__ ht,
        const float* __restrict__ hs,
        const float* __restrict__ adj,
        const float4* __restrict__ statT,
        const float4* __restrict__ statS,
        const float* __restrict__ wstat,
        float4* __restrict__ amr) {
    extern __shared__ float dsm[];
    float* hts = dsm;                 // 32*132
    float* hss = dsm + 32 * 132;      // 64*132
    int base  = blockIdx.x * 32;      // i base
    int b     = base >> 8;
    int jbase = blockIdx.y * 64;
    int t = threadIdx.x;
#pragma unroll
    for (int c = 0; c < 4; c++) {     // hts: 4096 floats
        int idx = c * 1024 + t * 4;
        int row = idx >> 7, col = idx & 127;
        *(float4*)&hts[row * 132 + col] = *(const float4*)(ht + base * Dc + idx);
    }
#pragma unroll
    for (int c = 0; c < 8; c++) {     // hss: 8192 floats
        int idx = c * 1024 + t * 4;
        int row = idx >> 7, col = idx & 127;
        *(float4*)&hss[row * 132 + col] =
            *(const float4*)(hs + (b * Nc + jbase) * Dc + idx);
    }
    __syncthreads();

    int w = t >> 5, l = t & 31;
    int rbase = w * 4;                // this warp's 4 i-rows
    float acc[8];                     // [i][jj]: i*2+jj, jj=0 -> j=l, jj=1 -> j=l+32
#pragma unroll
    for (int r = 0; r < 8; r++) acc[r] = 0.0f;
#pragma unroll 2
    for (int k4 = 0; k4 < 32; k4++) {
        float4 h0 = *(float4*)&hss[l * 132 + k4 * 4];
        float4 h1 = *(float4*)&hss[(l + 32) * 132 + k4 * 4];
#pragma unroll
        for (int i = 0; i < 4; i++) {
            float4 x4 = *(float4*)&hts[(rbase + i) * 132 + k4 * 4];
            float a0 = acc[i * 2], a1 = acc[i * 2 + 1];
            a0 = fmaf(x4.x, h0.x, a0); a1 = fmaf(x4.x, h1.x, a1);
            a0 = fmaf(x4.y, h0.y, a0); a1 = fmaf(x4.y, h1.y, a1);
            a0 = fmaf(x4.z, h0.z, a0); a1 = fmaf(x4.z, h1.z, a1);
            a0 = fmaf(x4.w, h0.w, a0); a1 = fmaf(x4.w, h1.w, a1);
            acc[i * 2] = a0; acc[i * 2 + 1] = a1;
        }
    }

    float Sw = __ldg(wstat), Qw = __ldg(wstat + 1);
#pragma unroll
    for (int jj = 0; jj < 2; jj++) {
        int j = jbase + l + jj * 32;
        float4 S = statS[b * Nc + j];
#pragma unroll
        for (int i = 0; i < 4; i++) {
            int row = base + rbase + i;
            float4 T = __ldg(statT + row);           // broadcast within warp
            float a  = adj[row * Nc + j];
            float mu   = fmaf(a, Sw, T.x + S.x);
            float sq   = fmaf(2.0f, acc[i * 2 + jj], T.y + S.y);
            sq         = fmaf(a, fmaf(a, Qw, T.z + S.z), sq);
            float var  = fmaf(sq, 1.0f / 128.0f, -mu * mu);
            float rv   = rsqrtf(var + 1e-5f);
            amr[row * Nc + j] = make_float4(a, rv, -mu * rv, 0.0f);
        }
    }
}

// ---------------- fused message + update ------------------------------------
__global__ void __launch_bounds__(256) msg_upd_kernel(
        const float* __restrict__ ht,
        const float* __restrict__ hs,
        const float* __restrict__ wjv,
        const float* __restrict__ g,
        const float* __restrict__ be,
        const float4* __restrict__ amr,
        float* __restrict__ h,
        const float* __restrict__ Wu,
        const float* __restrict__ bu,
        const float* __restrict__ ug,
        const float* __restrict__ ube) {
    __shared__ float cat[8][260];
    __shared__ float part[8][132];
    __shared__ float ubuf[8][132];
    int t = threadIdx.x;
    int warp = t >> 5;
    int lane = t & 31;
    int base = blockIdx.x * 8;
    int node = base + warp;
    int b = base >> 8;
    int i = node & 255;
    int d4 = lane << 2;

#pragma unroll
    for (int c = 0; c < 4; c++) {
        int idx = c * 256 + t;
        cat[idx >> 7][idx & 127] = h[base * Dc + idx];
    }

    // ---- msg phase ----
    const ulonglong2 HT = *(const ulonglong2*)(ht + node * Dc + d4);
    const ulonglong2 WJ = *(const ulonglong2*)(wjv + d4);
    float4 G4 = *(const float4*)(g + d4);
    float4 B4 = *(const float4*)(be + d4);
    u64 Gh01 = pk2(0.5f * G4.x, 0.5f * G4.y);
    u64 Gh23 = pk2(0.5f * G4.z, 0.5f * G4.w);
    u64 Bh01 = pk2(0.5f * B4.x, 0.5f * B4.y);
    u64 Bh23 = pk2(0.5f * B4.z, 0.5f * B4.w);

    const float* hsb = hs + b * Nc * Dc;
    const float4* arow = amr + node * Nc;

    u64 aP0 = 0, aP1 = 0, aT0 = 0, aT1 = 0;

#pragma unroll 4
    for (int j = 0; j < Nc; j++) {
        float4 m = __ldg(arow + j);              // {a, r, -mu*r, _}
        ulonglong2 sv = *(const ulonglong2*)(hsb + j * Dc + d4);
        u64 a2  = pk2(m.x, m.x);
        u64 r2  = pk2(m.y, m.y);
        u64 nm2 = pk2(m.z, m.z);
        u64 p0  = fma2v(a2, WJ.x, add2v(HT.x, sv.x));
        u64 p1  = fma2v(a2, WJ.y, add2v(HT.y, sv.y));
        u64 z0  = fma2v(p0, r2, nm2);
        u64 z1  = fma2v(p1, r2, nm2);
        u64 y0  = fma2v(z0, Gh01, Bh01);
        u64 y1  = fma2v(z1, Gh23, Bh23);
        float f0, f1, f2, f3;
        upk2(y0, f0, f1); upk2(y1, f2, f3);
        u64 t0 = pk2(tanh_ap(f0), tanh_ap(f1));
        u64 t1 = pk2(tanh_ap(f2), tanh_ap(f3));
        aP0 = add2v(aP0, y0);  aP1 = add2v(aP1, y1);
        aT0 = fma2v(y0, t0, aT0);
        aT1 = fma2v(y1, t1, aT1);
    }

    float ax, ay, az, aw;
    upk2(add2v(aP0, aT0), ax, ay);
    upk2(add2v(aP1, aT1), az, aw);

    // subtract diagonal j == i
    {
        float4 m = arow[i];
        const float4 s = *(const float4*)(hsb + i * Dc + d4);
        float h0, h1, h2, h3, w0, w1, w2, w3, g0, g1, g2, g3, e0, e1, e2, e3;
        upk2(HT.x, h0, h1); upk2(HT.y, h2, h3);
        upk2(WJ.x, w0, w1); upk2(WJ.y, w2, w3);
        upk2(Gh01, g0, g1); upk2(Gh23, g2, g3);
        upk2(Bh01, e0, e1); upk2(Bh23, e2, e3);
        float a = m.x, r = m.y, nmr = m.z;
        float p, z, y2;
        p = fmaf(a, w0, h0 + s.x); z = fmaf(p, r, nmr); y2 = fmaf(z, g0, e0); ax -= fmaf(y2, tanh_ap(y2), y2);
        p = fmaf(a, w1, h1 + s.y); z = fmaf(p, r, nmr); y2 = fmaf(z, g1, e1); ay -= fmaf(y2, tanh_ap(y2), y2);
        p = fmaf(a, w2, h2 + s.z); z = fmaf(p, r, nmr); y2 = fmaf(z, g2, e2); az -= fmaf(y2, tanh_ap(y2), y2);
        p = fmaf(a, w3, h3 + s.w); z = fmaf(p, r, nmr); y2 = fmaf(z, g3, e3); aw -= fmaf(y2, tanh_ap(y2), y2);
    }
    *(float4*)&cat[warp][Dc + d4] = make_float4(ax, ay, az, aw);
    __syncthreads();

    // ---- update phase: split-K GEMM ----
    int wg = t >> 7, tl = t & 127;
    float acc[8];
    float bv = wg ? 0.0f : bu[tl];
#pragma unroll
    for (int r = 0; r < 8; r++) acc[r] = bv;
    const float* Wp = Wu + wg * Dc * Dc;
    int kb = wg * Dc;
#pragma unroll 4
    for (int k4 = 0; k4 < 32; k4++) {
        float wk[4];
#pragma unroll
        for (int kk = 0; kk < 4; kk++) wk[kk] = Wp[(k4 * 4 + kk) * Dc + tl];
#pragma unroll
        for (int r = 0; r < 8; r++) {
            float4 x4 = *(float4*)&cat[r][kb + k4 * 4];
            acc[r] = fmaf(x4.x, wk[0], acc[r]);
            acc[r] = fmaf(x4.y, wk[1], acc[r]);
            acc[r] = fmaf(x4.z, wk[2], acc[r]);
            acc[r] = fmaf(x4.w, wk[3], acc[r]);
        }
    }
    if (wg == 1) {
#pragma unroll
        for (int r = 0; r < 8; r++) part[r][tl] = acc[r];
    }
    __syncthreads();
    if (wg == 0) {
#pragma unroll
        for (int r = 0; r < 8; r++) ubuf[r][tl] = acc[r] + part[r][tl];
    }
    __syncthreads();
    float4 u4 = *(float4*)&ubuf[warp][lane * 4];
    float s = (u4.x + u4.y) + (u4.z + u4.w);
    float q = fmaf(u4.x, u4.x, fmaf(u4.y, u4.y, fmaf(u4.z, u4.z, u4.w * u4.w)));
#pragma unroll
    for (int o = 16; o; o >>= 1) {
        s += __shfl_xor_sync(0xffffffffu, s, o);
        q += __shfl_xor_sync(0xffffffffu, q, o);
    }
    float mu  = s * (1.0f / 128.0f);
    float var = fmaf(q, 1.0f / 128.0f, -mu * mu);
    float rv  = rsqrtf(var + 1e-5f);
    float4 g4  = *(const float4*)(ug + lane * 4);
    float4 be4 = *(const float4*)(ube + lane * 4);
    float4 c4  = *(float4*)&cat[warp][lane * 4];
    float4 o4;
    o4.x = c4.x + silu_f(fmaf((u4.x - mu) * rv, g4.x, be4.x));
    o4.y = c4.y + silu_f(fmaf((u4.y - mu) * rv, g4.y, be4.y));
    o4.z = c4.z + silu_f(fmaf((u4.z - mu) * rv, g4.z, be4.z));
    o4.w = c4.w + silu_f(fmaf((u4.w - mu) * rv, g4.w, be4.w));
    *(float4*)(h + node * Dc + lane * 4) = o4;
}

// ---------------- fused decoder: e1 on the fly + 2-layer MLP ----------------
__global__ void __launch_bounds__(256) edge_kernel(
        const float* __restrict__ p, const float* __restrict__ q,
        const int* __restrict__ ei, const float* __restrict__ ea,
        const float* __restrict__ w1c,
        const float* __restrict__ W2,
        const float* __restrict__ b2,
        const float* __restrict__ w3,
        const float* __restrict__ b3,
        float* __restrict__ out) {
    __shared__ float2 W2s[Dc * 32];
    __shared__ float w1cs[Dc];
    __shared__ float w3s[64], b2s[64];
    __shared__ float e1s[8][132];
    int t = threadIdx.x;
    for (int i = t; i < Dc * 32; i += 256) {
        int k = i >> 5, c = i & 31;
        W2s[i] = make_float2(W2[k * 64 + c], W2[k * 64 + c + 32]);
    }
    if (t < Dc) w1cs[t] = w1c[t];
    if (t < 64) { w3s[t] = w3[t]; b2s[t] = b2[t]; }
    __syncthreads();
    float b3v = b3[0];
    int warp = t >> 5, lane = t & 31;
    int gw = blockIdx.x * 8 + warp;
    int nW = gridDim.x * 8;
    for (int e = gw; e < Ec; e += nW) {
        int u = ei[e];
        int v = ei[Ec + e];
        float a = ea[e];
        float4 pv = *(const float4*)(p + u * Dc + lane * 4);
        float4 qv = *(const float4*)(q + v * Dc + lane * 4);
        float4 wc = *(const float4*)(w1cs + lane * 4);
        float4 y;
        y.x = silu_f(fmaf(a, wc.x, pv.x + qv.x));
        y.y = silu_f(fmaf(a, wc.y, pv.y + qv.y));
        y.z = silu_f(fmaf(a, wc.z, pv.z + qv.z));
        y.w = silu_f(fmaf(a, wc.w, pv.w + qv.w));
        *(float4*)&e1s[warp][lane * 4] = y;
        __syncwarp();
        float a0 = b2s[lane], a1 = b2s[lane + 32];
#pragma unroll 4
        for (int k4 = 0; k4 < 32; k4++) {
            float4 s4 = *(float4*)&e1s[warp][k4 * 4];
            float2 w0 = W2s[(k4 * 4 + 0) * 32 + lane];
            float2 w1 = W2s[(k4 * 4 + 1) * 32 + lane];
            float2 w2 = W2s[(k4 * 4 + 2) * 32 + lane];
            float2 w3v = W2s[(k4 * 4 + 3) * 32 + lane];
            a0 = fmaf(s4.x, w0.x, a0); a1 = fmaf(s4.x, w0.y, a1);
            a0 = fmaf(s4.y, w1.x, a0); a1 = fmaf(s4.y, w1.y, a1);
            a0 = fmaf(s4.z, w2.x, a0); a1 = fmaf(s4.z, w2.y, a1);
            a0 = fmaf(s4.w, w3v.x, a0); a1 = fmaf(s4.w, w3v.y, a1);
        }
        a0 = silu_f(a0);
        a1 = silu_f(a1);
        float tt = fmaf(a0, w3s[lane], a1 * w3s[lane + 32]);
#pragma unroll
        for (int o = 16; o; o >>= 1) tt += __shfl_xor_sync(0xffffffffu, tt, o);
        if (lane == 0) out[e] = tanhf(tt + b3v);
        __syncwarp();
    }
}

// ---------------- launch ----------------------------------------------------
extern "C" void kernel_launch(void* const* d_in, const int* in_sizes, int n_in,
                              void* d_out, int out_size) {
    const float* x     = (const float*)d_in[0];
    const int*   ei    = (const int*)  d_in[1];
    const float* ea    = (const float*)d_in[2];
    const float* encW  = (const float*)d_in[4];
    const float* encb  = (const float*)d_in[5];
    const float* msgW  = (const float*)d_in[6];
    const float* msgb  = (const float*)d_in[7];
    const float* msgg  = (const float*)d_in[8];
    const float* msgbe = (const float*)d_in[9];
    const float* updW  = (const float*)d_in[10];
    const float* updb  = (const float*)d_in[11];
    const float* updg  = (const float*)d_in[12];
    const float* updbe = (const float*)d_in[13];
    const float* decW1 = (const float*)d_in[14];
    const float* decb1 = (const float*)d_in[15];
    const float* decW2 = (const float*)d_in[16];
    const float* decb2 = (const float*)d_in[17];
    const float* decW3 = (const float*)d_in[18];
    const float* decb3 = (const float*)d_in[19];
    float* out = (float*)d_out;

    float *adj, *h, *ht, *hs, *p, *q, *wst;
    float4 *amr, *sT, *sS;
    cudaGetSymbolAddress((void**)&adj, g_adj);
    cudaGetSymbolAddress((void**)&h,   g_h);
    cudaGetSymbolAddress((void**)&ht,  g_ht);
    cudaGetSymbolAddress((void**)&hs,  g_hs);
    cudaGetSymbolAddress((void**)&p,   g_p);
    cudaGetSymbolAddress((void**)&q,   g_q);
    cudaGetSymbolAddress((void**)&amr, g_amr);
    cudaGetSymbolAddress((void**)&sT,  g_statT);
    cudaGetSymbolAddress((void**)&sS,  g_statS);
    cudaGetSymbolAddress((void**)&wst, g_wstat);

    const int CDOT_SMEM = (32 * 132 + 64 * 132) * 4;   // 50688 B
    cudaFuncSetAttribute(cdot_mr_kernel,
                         cudaFuncAttributeMaxDynamicSharedMemorySize,
                         CDOT_SMEM);

    prep_kernel<<<1089, 256>>>(x, encW, encb, msgW, adj, h, wst);
    scatter_adj_kernel<<<(Ec + 255) / 256, 256>>>(ei, ea, adj);

    for (int l = 0; l < Lc; l++) {
        const float* Wl  = msgW + (size_t)l * 257 * Dc;
        const float* wjv = Wl + 2 * Dc * Dc;
        dual_mm_ns<true><<<BN / 8, 256>>>(h, Wl, Wl + Dc * Dc, msgb + l * Dc,
                                          wjv, ht, hs, sT, sS);
        cdot_mr_kernel<<<dim3(BN / 32, Nc / 64), 256, CDOT_SMEM>>>(
            ht, hs, adj, sT, sS, wst + 2 * l, amr);
        msg_upd_kernel<<<BN / 8, 256>>>(ht, hs, wjv,
                                        msgg + l * Dc, msgbe + l * Dc, amr, h,
                                        updW + (size_t)l * 2 * Dc * Dc,
                                        updb + l * Dc, updg + l * Dc, updbe + l * Dc);
    }

    dual_mm_ns<false><<<BN / 8, 256>>>(h, decW1, decW1 + Dc * Dc, decb1,
                                       nullptr, p, q, nullptr, nullptr);
    edge_kernel<<<512, 256>>>(p, q, ei, ea, decW1 + 2 * Dc * Dc,
                              decW2, decb2, decW3, decb3, out);
}